// round 12
// baseline (speedup 1.0000x reference)
#include <cuda_runtime.h>
#include <math.h>

#define SS   4096      // 64*64
#define SSS  262144    // 64^3
#define CH   64

typedef unsigned long long u64;

// Scratch (device globals). att1/att2 are batch-interleaved float2 = (b0,b1).
__device__ float4 g_att1[CH*SSS/2];
__device__ float4 g_att2[CH*SSS/2];
__device__ float2 g_pooled2[2*SSS];    // [ic={mean,max}][s] -> (b0,b1)
__device__ float  g_gate[2*2*SSS];     // [b][{g0,g1}][s]

__device__ __forceinline__ u64 pk2(float lo, float hi) {
    u64 r; asm("mov.b64 %0, {%1, %2};" : "=l"(r) : "f"(lo), "f"(hi)); return r;
}
__device__ __forceinline__ void ffma2(u64& d, u64 a, u64 b) {
    asm("fma.rn.f32x2 %0, %1, %2, %0;" : "+l"(d) : "l"(a), "l"(b));
}

// ---------------- conv1: depthwise 5x5x5, pad 2, batch-packed ---------------
// z-major smem columns: column (sy,sx) holds 20 z f2 at stride CZ1=21 (odd).
// 128 threads = lx(16) x ly(8); thread = one (y,x) column x 16 z outputs.
// Warp phase = 16 contiguous lx -> banks 21*dlx === 5*dlx mod 16, all distinct
// -> conflict-free LDS.64.
#define CZ1 21
__global__ __launch_bounds__(128) void k_conv1(const float* __restrict__ x,
                                               const float* __restrict__ w1,
                                               const float* __restrict__ b1) {
    __shared__ float2 sh[240*CZ1];               // 5040 f2 = 40320 B
    __shared__ float2 swt[125];

    const int bx = blockIdx.x, c = blockIdx.y;   // bx: tx(4) ty(8) tz(4)
    const int tx = bx & 3, ty = (bx >> 2) & 7, tz = bx >> 5;
    const int x0 = tx*16, y0 = ty*8, z0 = tz*16;
    const int tid = threadIdx.x;

    const float* __restrict__ x0p = x + (size_t)c * SSS;
    const float* __restrict__ x1p = x + (size_t)(CH + c) * SSS;

    if (tid < 125) { float w = w1[c*125 + tid]; swt[tid] = make_float2(w, w); }

    // halo: 12 y-rows x 20 x-cols, each column 20 z
    for (int cp = tid; cp < 240; cp += 128) {
        const int sy = cp / 20, sx = cp % 20;
        const int gy = y0 - 2 + sy, gx = x0 - 2 + sx;
        const bool vyx = ((unsigned)gy < 64u) && ((unsigned)gx < 64u);
        const int gb = gy*64 + gx;
        const int base = cp * CZ1;
#pragma unroll 4
        for (int sz = 0; sz < 20; sz++) {
            const int gz = z0 - 2 + sz;
            float2 v = make_float2(0.f, 0.f);
            if (vyx && (unsigned)gz < 64u) {
                const int o = gz*SS + gb;
                v.x = x0p[o]; v.y = x1p[o];
            }
            sh[base + sz] = v;
        }
    }
    __syncthreads();

    const int lx = tid & 15, ly = tid >> 4;

    u64 acc[16];
    const float bias = b1[c];
    const u64 bpk = pk2(bias, bias);
#pragma unroll
    for (int z = 0; z < 16; z++) acc[z] = bpk;

#pragma unroll 1
    for (int ky = 0; ky < 5; ky++) {
#pragma unroll 1
        for (int kx = 0; kx < 5; kx++) {
            const int base = ((ly + ky)*20 + lx + kx) * CZ1;
            u64 col[20];
#pragma unroll
            for (int j = 0; j < 20; j++)
                col[j] = *(const u64*)&sh[base + j];
#pragma unroll
            for (int kz = 0; kz < 5; kz++) {
                const u64 w = *(const u64*)&swt[kz*25 + ky*5 + kx];
#pragma unroll
                for (int z = 0; z < 16; z++)
                    ffma2(acc[z], col[z + kz], w);
            }
        }
    }

    float2* __restrict__ oc = (float2*)g_att1 + (size_t)c * SSS;
    const int ob = (y0 + ly)*64 + (x0 + lx);
#pragma unroll
    for (int z = 0; z < 16; z++)
        *(u64*)&oc[(z0 + z)*SS + ob] = acc[z];
}

// ---------------- conv2: depthwise 7x7x7, dilation 3, pad 9 -----------------
// Residue decomposition (mod 3) -> dense 7-tap conv on 21/22-wide subgrid.
// z-major columns: column (sy,sx) holds 28 subgrid-z f2 at stride CZ2=29 (odd,
// +1 pad). 128 threads = lx(8) x hz(2) x ly(8); hz z-split 12/10 (j-offset 12).
// Phase=(lx,hz): dbank = 13*dlx + 12*dhz mod 16, no zero in range -> clean.
#define CZ2 29
__global__ __launch_bounds__(128) void k_conv2(const float* __restrict__ w2,
                                               const float* __restrict__ b2) {
    __shared__ float2 sh[196*CZ2 + 2];           // 5686 f2 = 45488 B (+ovf pad)
    __shared__ float swts[343];                  // scalar weights, 1372 B

    const int blk = blockIdx.x;                  // 27 residues * 9 yx tiles
    const int c = blockIdx.y;
    const int res = blk / 9, t = blk % 9;
    const int rz = res / 9, ry = (res / 3) % 3, rx = res % 3;
    const int tyi = t / 3, txi = t % 3;
    const int Lz = (rz == 0) ? 22 : 21;
    const int Ly = (ry == 0) ? 22 : 21;
    const int Lx = (rx == 0) ? 22 : 21;

    const int tid = threadIdx.x;
    const float2* __restrict__ icp = (const float2*)g_att1 + (size_t)c * SSS;

    for (int s = tid; s < 343; s += 128) swts[s] = w2[c*343 + s];

    const int uy0 = tyi*8, ux0 = txi*8;
    // halo: 14x14 columns, 28 z each
    for (int cp = tid; cp < 196; cp += 128) {
        const int sy = cp / 14, sx = cp % 14;
        const int gy = ry + 3*(uy0 + sy - 3);
        const int gx = rx + 3*(ux0 + sx - 3);
        const bool vyx = ((unsigned)gy < 64u) && ((unsigned)gx < 64u);
        const int gb = gy*64 + gx;
        const int base = cp * CZ2;
#pragma unroll 4
        for (int sz = 0; sz < 28; sz++) {
            const int gz = rz + 3*(sz - 3);
            float2 v = make_float2(0.f, 0.f);
            if (vyx && (unsigned)gz < 64u)
                v = icp[gz*SS + gb];
            sh[base + sz] = v;
        }
    }
    __syncthreads();

    const int lx = tid & 7;
    const int hz = (tid >> 3) & 1;               // z block: u 0..11 / 12..21
    const int ly = tid >> 4;                     // 0..7
    const int uy = uy0 + ly;
    const int j0 = 12*hz;

    u64 acc[12];
    const float bias = b2[c];
    const u64 bpk = pk2(bias, bias);
#pragma unroll
    for (int l = 0; l < 12; l++) acc[l] = bpk;

#pragma unroll 1
    for (int ky = 0; ky < 7; ky++) {
#pragma unroll 1
        for (int kx = 0; kx < 7; kx++) {
            const int base = ((ly + ky)*14 + lx + kx) * CZ2 + j0;
            u64 col[18];
#pragma unroll
            for (int j = 0; j < 18; j++)
                col[j] = *(const u64*)&sh[base + j];
            u64 wr[7];
#pragma unroll
            for (int kz = 0; kz < 7; kz++) {
                const float w = swts[kz*49 + ky*7 + kx];
                wr[kz] = pk2(w, w);
            }
#pragma unroll
            for (int kz = 0; kz < 7; kz++) {
#pragma unroll
                for (int l = 0; l < 12; l++)
                    ffma2(acc[l], col[l + kz], wr[kz]);
            }
        }
    }

    const int ux = ux0 + lx;
    if (uy < Ly && ux < Lx) {
        float2* __restrict__ oc = (float2*)g_att2 + (size_t)c*SSS;
        const int gy = ry + 3*uy, gx = rx + 3*ux;
        const int ob = gy*64 + gx;
#pragma unroll
        for (int l = 0; l < 12; l++) {
            const int u = 12*hz + l;
            if (u < Lz)
                *(u64*)&oc[(rz + 3*u)*SS + ob] = acc[l];
        }
    }
}

// ---------------- pool: channel mean + max over [att1; att2], both batches --
__global__ __launch_bounds__(256) void k_pool() {
    const int s = blockIdx.x * 256 + threadIdx.x;       // over SSS
    const float2* p1 = (const float2*)g_att1 + s;
    const float2* p2 = (const float2*)g_att2 + s;
    float s0 = 0.f, s1 = 0.f, m0 = -INFINITY, m1 = -INFINITY;
#pragma unroll 8
    for (int c = 0; c < 64; c++) {
        float2 v = p1[(size_t)c*SSS];
        s0 += v.x; s1 += v.y; m0 = fmaxf(m0, v.x); m1 = fmaxf(m1, v.y);
    }
#pragma unroll 8
    for (int c = 0; c < 64; c++) {
        float2 v = p2[(size_t)c*SSS];
        s0 += v.x; s1 += v.y; m0 = fmaxf(m0, v.x); m1 = fmaxf(m1, v.y);
    }
    g_pooled2[s]       = make_float2(s0 * (1.f/128.f), s1 * (1.f/128.f));
    g_pooled2[SSS + s] = make_float2(m0, m1);
}

// ---------------- gate: 2->2 conv 7x7x7 pad 3, sigmoid (scalar, per batch) --
__global__ __launch_bounds__(128) void k_gate(const float* __restrict__ ws,
                                              const float* __restrict__ bs) {
    const int tile = blockIdx.x;                 // tz(8) ty(4) tx(8) = 256
    const int b = blockIdx.y;
    const int tz = tile >> 5, ty = (tile >> 3) & 3, tx = tile & 7;
    const int z0 = tz*8, y0 = ty*16, x0 = tx*8;

    __shared__ float sh[2*14*22*14];
    __shared__ float swt[1372];
    const int tid = threadIdx.x;

    for (int s = tid; s < 1372; s += 128) swt[s] = ws[s];
    for (int s = tid; s < 2*14*22*14; s += 128) {
        int icc = s / 4312, r = s % 4312;
        int sz = r / 308, r2 = r % 308, sy = r2 / 14, sx = r2 % 14;
        int gz = z0-3+sz, gy = y0-3+sy, gx = x0-3+sx;
        float v = 0.f;
        if ((unsigned)gz < 64u && (unsigned)gy < 64u && (unsigned)gx < 64u) {
            float2 p = g_pooled2[icc*SSS + gz*SS + gy*64 + gx];
            v = b ? p.y : p.x;
        }
        sh[s] = v;
    }
    __syncthreads();

    const int ly = tid >> 3, lx = tid & 7;
    float acc0[8], acc1[8];
    const float bias0 = bs[0], bias1 = bs[1];
#pragma unroll
    for (int z = 0; z < 8; z++) { acc0[z] = bias0; acc1[z] = bias1; }

#pragma unroll 1
    for (int icc = 0; icc < 2; icc++)
#pragma unroll 1
    for (int ky = 0; ky < 7; ky++)
#pragma unroll 1
    for (int kx = 0; kx < 7; kx++) {
        float col[14];
#pragma unroll
        for (int j = 0; j < 14; j++)
            col[j] = sh[icc*4312 + j*308 + (ly+ky)*14 + lx + kx];
#pragma unroll
        for (int kz = 0; kz < 7; kz++) {
            const float w0 = swt[icc*343 + kz*49 + ky*7 + kx];
            const float w1 = swt[686 + icc*343 + kz*49 + ky*7 + kx];
#pragma unroll
            for (int z = 0; z < 8; z++) {
                acc0[z] = fmaf(col[z+kz], w0, acc0[z]);
                acc1[z] = fmaf(col[z+kz], w1, acc1[z]);
            }
        }
    }

    float* g0 = g_gate + (size_t)b*2*SSS;
#pragma unroll
    for (int z = 0; z < 8; z++) {
        const int o = (z0+z)*SS + (y0+ly)*64 + (x0+lx);
        g0[o]       = 1.f/(1.f + __expf(-acc0[z]));
        g0[SSS + o] = 1.f/(1.f + __expf(-acc1[z]));
    }
}

// ---------------- combine: out = att1*g0 + att2*g1 + x ----------------------
__global__ __launch_bounds__(256) void k_combine(const float* __restrict__ x,
                                                 float* __restrict__ out) {
    const int i = blockIdx.x * 256 + threadIdx.x;      // 8,388,608 threads
    const int c = i >> 17;                              // SSS/2 per channel
    const int s = (i & 131071) << 1;
    const float4 a1 = *(const float4*)((const float*)g_att1 + ((size_t)c*SSS + s)*2);
    const float4 a2 = *(const float4*)((const float*)g_att2 + ((size_t)c*SSS + s)*2);

    // batch 0
    {
        const float2 xv = *(const float2*)(x + (size_t)c*SSS + s);
        const float2 g0 = *(const float2*)(g_gate + s);
        const float2 g1 = *(const float2*)(g_gate + SSS + s);
        float2 o;
        o.x = fmaf(a1.x, g0.x, fmaf(a2.x, g1.x, xv.x));
        o.y = fmaf(a1.z, g0.y, fmaf(a2.z, g1.y, xv.y));
        *(float2*)(out + (size_t)c*SSS + s) = o;
    }
    // batch 1
    {
        const float2 xv = *(const float2*)(x + (size_t)(CH + c)*SSS + s);
        const float2 g0 = *(const float2*)(g_gate + 2*SSS + s);
        const float2 g1 = *(const float2*)(g_gate + 3*SSS + s);
        float2 o;
        o.x = fmaf(a1.y, g0.x, fmaf(a2.y, g1.x, xv.x));
        o.y = fmaf(a1.w, g0.y, fmaf(a2.w, g1.y, xv.y));
        *(float2*)(out + (size_t)(CH + c)*SSS + s) = o;
    }
}

extern "C" void kernel_launch(void* const* d_in, const int* in_sizes, int n_in,
                              void* d_out, int out_size) {
    const float* x  = (const float*)d_in[0];
    const float* w1 = (const float*)d_in[1];
    const float* b1 = (const float*)d_in[2];
    const float* w2 = (const float*)d_in[3];
    const float* b2 = (const float*)d_in[4];
    const float* ws = (const float*)d_in[5];
    const float* bs = (const float*)d_in[6];
    float* out = (float*)d_out;

    k_conv1<<<dim3(128, 64), 128>>>(x, w1, b1);
    k_conv2<<<dim3(243, 64), 128>>>(w2, b2);
    k_pool<<<1024, 256>>>();
    k_gate<<<dim3(256, 2), 128>>>(ws, bs);
    k_combine<<<32768, 256>>>(x, out);
}

// round 14
// speedup vs baseline: 1.0969x; 1.0969x over previous
#include <cuda_runtime.h>
#include <math.h>

#define SS   4096      // 64*64
#define SSS  262144    // 64^3
#define CH   64

typedef unsigned long long u64;

// Scratch (device globals). att1/att2 are batch-interleaved: element (c*SSS+s)
// is a float2 = (batch0, batch1). float4 decl for 16B alignment.
__device__ float4 g_att1[CH*SSS/2];
__device__ float4 g_att2[CH*SSS/2];
__device__ float2 g_pooled2[2*SSS];    // [ic={mean,max}][s] -> (b0,b1)
__device__ float  g_gate[2*2*SSS];     // [b][{g0,g1}][s]

__device__ __forceinline__ u64 pk2(float lo, float hi) {
    u64 r; asm("mov.b64 %0, {%1, %2};" : "=l"(r) : "f"(lo), "f"(hi)); return r;
}
__device__ __forceinline__ void ffma2(u64& d, u64 a, u64 b) {
    asm("fma.rn.f32x2 %0, %1, %2, %0;" : "+l"(d) : "l"(a), "l"(b));
}

// ---------------- conv1: depthwise 5x5x5, pad 2, both batches packed --------
// tile: z=16, y=8, x=16; 128 threads = lx(16) x ly(8); thread computes a
// z-column of 16 packed outputs (FFMA2:LDS.64 = 80:25 per tap-group).
// Warp phase = 16 contiguous lx -> conflict-free LDS.64.
__global__ __launch_bounds__(128) void k_conv1(const float* __restrict__ x,
                                               const float* __restrict__ w1,
                                               const float* __restrict__ b1) {
    __shared__ float2 sh[20*12*20];              // 4800 f2 = 38400 B
    __shared__ float2 swt[125];

    const int bx = blockIdx.x, c = blockIdx.y;   // bx: tz(4) ty(8) tx(4)
    const int tz = bx >> 5, ty = (bx >> 2) & 7, tx = bx & 3;
    const int z0 = tz * 16, y0 = ty * 8, x0 = tx * 16;
    const int tid = threadIdx.x;

    const float* __restrict__ x0p = x + (size_t)c * SSS;
    const float* __restrict__ x1p = x + (size_t)(CH + c) * SSS;

    if (tid < 125) { float w = w1[c*125 + tid]; swt[tid] = make_float2(w, w); }

    // halo: 20z x 12y x 20x
    for (int s = tid; s < 20*12*20; s += 128) {
        const int sz = s / 240, r = s % 240, sy = r / 20, sx = r % 20;
        const int gz = z0 - 2 + sz, gy = y0 - 2 + sy, gx = x0 - 2 + sx;
        float2 v = make_float2(0.f, 0.f);
        if ((unsigned)gz < 64u && (unsigned)gy < 64u && (unsigned)gx < 64u) {
            const int o = gz*SS + gy*64 + gx;
            v.x = x0p[o]; v.y = x1p[o];
        }
        sh[s] = v;
    }
    __syncthreads();

    const int lx = tid & 15, ly = tid >> 4;

    u64 acc[16];
    const float bias = b1[c];
    const u64 bpk = pk2(bias, bias);
#pragma unroll
    for (int z = 0; z < 16; z++) acc[z] = bpk;

#pragma unroll 1
    for (int ky = 0; ky < 5; ky++) {
        const int rowb = (ly + ky) * 20 + lx;
#pragma unroll 1
        for (int kx = 0; kx < 5; kx++) {
            u64 col[20];
#pragma unroll
            for (int j = 0; j < 20; j++)
                col[j] = *(const u64*)&sh[j*240 + rowb + kx];
#pragma unroll
            for (int kz = 0; kz < 5; kz++) {
                const u64 w = *(const u64*)&swt[kz*25 + ky*5 + kx];
#pragma unroll
                for (int z = 0; z < 16; z++)
                    ffma2(acc[z], col[z + kz], w);
            }
        }
    }

    float2* __restrict__ oc = (float2*)g_att1 + (size_t)c * SSS;
    const int ob = (y0 + ly)*64 + (x0 + lx);
#pragma unroll
    for (int z = 0; z < 16; z++)
        *(u64*)&oc[(z0 + z)*SS + ob] = acc[z];
}

// ---------------- conv2: depthwise 7x7x7, dilation 3, pad 9 -----------------
// Residue decomposition (mod 3) -> dense 7-tap conv on subsampled grid.
// smem: x-stride 14 float2, z-plane stride padded to C2_ZS=200 float2.
// Thread map: lx=tid&7, hz=(tid>>3)&1, ly=tid>>4. A 16-lane phase holds
// lx(0..7) x hz(0..1); phase addr mod 16 = lx + 8*hz (11*200=2200===8 mod 16)
// -> 16 distinct bank pairs -> conflict-free LDS.64. 47.5 KB static smem.
#define C2_ZS 200
__global__ __launch_bounds__(128) void k_conv2(const float* __restrict__ w2,
                                               const float* __restrict__ b2) {
    __shared__ float2 sh[28*C2_ZS];              // 44800 B
    __shared__ float2 swt[343];                  // 2744 B

    const int blk = blockIdx.x;                  // 27 residues * 9 yx tiles
    const int c = blockIdx.y;
    const int res = blk / 9, t = blk % 9;
    const int rz = res / 9, ry = (res / 3) % 3, rx = res % 3;
    const int tyi = t / 3, txi = t % 3;
    const int Lz = (rz == 0) ? 22 : 21;
    const int Ly = (ry == 0) ? 22 : 21;
    const int Lx = (rx == 0) ? 22 : 21;

    const int tid = threadIdx.x;
    const float2* __restrict__ icp = (const float2*)g_att1 + (size_t)c * SSS;
    for (int s = tid; s < 343; s += 128) { float w = w2[c*343 + s]; swt[s] = make_float2(w, w); }

    const int uy0 = tyi*8, ux0 = txi*8;
    for (int s = tid; s < 28*14*14; s += 128) {
        int sz = s / 196, r = s % 196, sy = r / 14, sx = r % 14;
        int gz = rz + 3*(sz - 3);
        int gy = ry + 3*(uy0 + sy - 3);
        int gx = rx + 3*(ux0 + sx - 3);
        float2 v = make_float2(0.f, 0.f);
        if ((unsigned)gz < 64u && (unsigned)gy < 64u && (unsigned)gx < 64u)
            v = icp[gz*SS + gy*64 + gx];
        sh[sz*C2_ZS + sy*14 + sx] = v;
    }
    __syncthreads();

    const int lx = tid & 7;
    const int hz = (tid >> 3) & 1;               // z half: u 0..10 / 11..21
    const int ly = tid >> 4;                     // 0..7
    const int uy = uy0 + ly, ux = ux0 + lx;
    const int zb = 11*hz;

    u64 acc[11];
    const float bias = b2[c];
    const u64 bpk = pk2(bias, bias);
#pragma unroll
    for (int l = 0; l < 11; l++) acc[l] = bpk;

#pragma unroll 1
    for (int ky = 0; ky < 7; ky++) {
        const int rowb = (ly + ky)*14 + lx;
#pragma unroll
        for (int kx = 0; kx < 7; kx++) {
            u64 col[17];
#pragma unroll
            for (int j = 0; j < 17; j++)
                col[j] = *(const u64*)&sh[(zb + j)*C2_ZS + rowb + kx];
#pragma unroll
            for (int kz = 0; kz < 7; kz++) {
                const u64 w = *(const u64*)&swt[kz*49 + ky*7 + kx];
#pragma unroll
                for (int l = 0; l < 11; l++)
                    ffma2(acc[l], col[l+kz], w);
            }
        }
    }

    if (uy < Ly && ux < Lx) {
        float2* __restrict__ oc = (float2*)g_att2 + (size_t)c*SSS;
        const int gy = ry + 3*uy, gx = rx + 3*ux;
#pragma unroll
        for (int l = 0; l < 11; l++) {
            const int u = zb + l;
            if (u < Lz)
                *(u64*)&oc[(rz + 3*u)*SS + gy*64 + gx] = acc[l];
        }
    }
}

// ---------------- pool: channel mean + max over [att1; att2], both batches --
__global__ __launch_bounds__(256) void k_pool() {
    const int s = blockIdx.x * 256 + threadIdx.x;       // over SSS
    const float2* p1 = (const float2*)g_att1 + s;
    const float2* p2 = (const float2*)g_att2 + s;
    float s0 = 0.f, s1 = 0.f, m0 = -INFINITY, m1 = -INFINITY;
#pragma unroll 8
    for (int c = 0; c < 64; c++) {
        float2 v = p1[(size_t)c*SSS];
        s0 += v.x; s1 += v.y; m0 = fmaxf(m0, v.x); m1 = fmaxf(m1, v.y);
    }
#pragma unroll 8
    for (int c = 0; c < 64; c++) {
        float2 v = p2[(size_t)c*SSS];
        s0 += v.x; s1 += v.y; m0 = fmaxf(m0, v.x); m1 = fmaxf(m1, v.y);
    }
    g_pooled2[s]       = make_float2(s0 * (1.f/128.f), s1 * (1.f/128.f));
    g_pooled2[SSS + s] = make_float2(m0, m1);
}

// ---------------- gate: 2->2 conv 7x7x7 pad 3, sigmoid (scalar, per batch) --
__global__ __launch_bounds__(128) void k_gate(const float* __restrict__ ws,
                                              const float* __restrict__ bs) {
    const int tile = blockIdx.x;                 // tz(8) ty(4) tx(8) = 256
    const int b = blockIdx.y;
    const int tz = tile >> 5, ty = (tile >> 3) & 3, tx = tile & 7;
    const int z0 = tz*8, y0 = ty*16, x0 = tx*8;

    __shared__ float sh[2*14*22*14];
    __shared__ float swt[1372];
    const int tid = threadIdx.x;

    for (int s = tid; s < 1372; s += 128) swt[s] = ws[s];
    for (int s = tid; s < 2*14*22*14; s += 128) {
        int icc = s / 4312, r = s % 4312;
        int sz = r / 308, r2 = r % 308, sy = r2 / 14, sx = r2 % 14;
        int gz = z0-3+sz, gy = y0-3+sy, gx = x0-3+sx;
        float v = 0.f;
        if ((unsigned)gz < 64u && (unsigned)gy < 64u && (unsigned)gx < 64u) {
            float2 p = g_pooled2[icc*SSS + gz*SS + gy*64 + gx];
            v = b ? p.y : p.x;
        }
        sh[s] = v;
    }
    __syncthreads();

    const int ly = tid >> 3, lx = tid & 7;
    float acc0[8], acc1[8];
    const float bias0 = bs[0], bias1 = bs[1];
#pragma unroll
    for (int z = 0; z < 8; z++) { acc0[z] = bias0; acc1[z] = bias1; }

#pragma unroll 1
    for (int icc = 0; icc < 2; icc++)
#pragma unroll 1
    for (int ky = 0; ky < 7; ky++)
#pragma unroll 1
    for (int kx = 0; kx < 7; kx++) {
        float col[14];
#pragma unroll
        for (int j = 0; j < 14; j++)
            col[j] = sh[icc*4312 + j*308 + (ly+ky)*14 + lx + kx];
#pragma unroll
        for (int kz = 0; kz < 7; kz++) {
            const float w0 = swt[icc*343 + kz*49 + ky*7 + kx];
            const float w1 = swt[686 + icc*343 + kz*49 + ky*7 + kx];
#pragma unroll
            for (int z = 0; z < 8; z++) {
                acc0[z] = fmaf(col[z+kz], w0, acc0[z]);
                acc1[z] = fmaf(col[z+kz], w1, acc1[z]);
            }
        }
    }

    float* g0 = g_gate + (size_t)b*2*SSS;
#pragma unroll
    for (int z = 0; z < 8; z++) {
        const int o = (z0+z)*SS + (y0+ly)*64 + (x0+lx);
        g0[o]       = 1.f/(1.f + __expf(-acc0[z]));
        g0[SSS + o] = 1.f/(1.f + __expf(-acc1[z]));
    }
}

// ---------------- combine: out = att1*g0 + att2*g1 + x ----------------------
__global__ __launch_bounds__(256) void k_combine(const float* __restrict__ x,
                                                 float* __restrict__ out) {
    const int i = blockIdx.x * 256 + threadIdx.x;      // 8,388,608 threads
    const int c = i >> 17;                              // SSS/2 per channel
    const int s = (i & 131071) << 1;
    const float4 a1 = *(const float4*)((const float*)g_att1 + ((size_t)c*SSS + s)*2);
    const float4 a2 = *(const float4*)((const float*)g_att2 + ((size_t)c*SSS + s)*2);

    // batch 0
    {
        const float2 xv = *(const float2*)(x + (size_t)c*SSS + s);
        const float2 g0 = *(const float2*)(g_gate + s);
        const float2 g1 = *(const float2*)(g_gate + SSS + s);
        float2 o;
        o.x = fmaf(a1.x, g0.x, fmaf(a2.x, g1.x, xv.x));
        o.y = fmaf(a1.z, g0.y, fmaf(a2.z, g1.y, xv.y));
        *(float2*)(out + (size_t)c*SSS + s) = o;
    }
    // batch 1
    {
        const float2 xv = *(const float2*)(x + (size_t)(CH + c)*SSS + s);
        const float2 g0 = *(const float2*)(g_gate + 2*SSS + s);
        const float2 g1 = *(const float2*)(g_gate + 3*SSS + s);
        float2 o;
        o.x = fmaf(a1.y, g0.x, fmaf(a2.y, g1.x, xv.x));
        o.y = fmaf(a1.w, g0.y, fmaf(a2.w, g1.y, xv.y));
        *(float2*)(out + (size_t)(CH + c)*SSS + s) = o;
    }
}

extern "C" void kernel_launch(void* const* d_in, const int* in_sizes, int n_in,
                              void* d_out, int out_size) {
    const float* x  = (const float*)d_in[0];
    const float* w1 = (const float*)d_in[1];
    const float* b1 = (const float*)d_in[2];
    const float* w2 = (const float*)d_in[3];
    const float* b2 = (const float*)d_in[4];
    const float* ws = (const float*)d_in[5];
    const float* bs = (const float*)d_in[6];
    float* out = (float*)d_out;

    k_conv1<<<dim3(128, 64), 128>>>(x, w1, b1);
    k_conv2<<<dim3(243, 64), 128>>>(w2, b2);
    k_pool<<<1024, 256>>>();
    k_gate<<<dim3(256, 2), 128>>>(ws, bs);
    k_combine<<<32768, 256>>>(x, out);
}

// round 15
// speedup vs baseline: 1.1754x; 1.0715x over previous
#include <cuda_runtime.h>
#include <math.h>

#define SS   4096      // 64*64
#define SSS  262144    // 64^3
#define CH   64

// residue layout constants
#define RES_U   22                 // padded u extent
#define RES_UU  484                // 22*22
#define RES_VOL 10648              // 22^3
#define RES_CH  287496             // 27 * 10648 (f2 per channel)

typedef unsigned long long u64;

// Scratch (device globals). att1 is stored residue-decomposed + batch-packed:
// element (c, r=(rz,ry,rx), uz, uy, ux) is float2 (batch0, batch1).
// att2 natural layout, batch-packed.
__device__ float4 g_att1r[CH*RES_CH/2 + 64];
__device__ float4 g_att2[CH*SSS/2];
__device__ float2 g_pooled2[2*SSS];    // [ic={mean,max}][s] -> (b0,b1)
__device__ float  g_gate[2*2*SSS];     // [b][{g0,g1}][s]

__device__ __forceinline__ u64 pk2(float lo, float hi) {
    u64 r; asm("mov.b64 %0, {%1, %2};" : "=l"(r) : "f"(lo), "f"(hi)); return r;
}
__device__ __forceinline__ void ffma2(u64& d, u64 a, u64 b) {
    asm("fma.rn.f32x2 %0, %1, %2, %0;" : "+l"(d) : "l"(a), "l"(b));
}

// map natural (g) -> (r, u)
__device__ __forceinline__ void r3(int g, int& r, int& u) { u = g / 3; r = g - 3*u; }

// ---------------- conv1: depthwise 5x5x5, pad 2, both batches packed --------
// tile: z=16, y=8, x=16; 128 threads = lx(16) x ly(8); thread computes a
// z-column of 16 packed outputs. Warp phase = 16 contiguous lx ->
// conflict-free LDS.64. Output scattered into residue layout.
__global__ __launch_bounds__(128) void k_conv1(const float* __restrict__ x,
                                               const float* __restrict__ w1,
                                               const float* __restrict__ b1) {
    __shared__ float2 sh[20*12*20];              // 4800 f2 = 38400 B
    __shared__ float2 swt[125];

    const int bx = blockIdx.x, c = blockIdx.y;   // bx: tz(4) ty(8) tx(4)
    const int tz = bx >> 5, ty = (bx >> 2) & 7, tx = bx & 3;
    const int z0 = tz * 16, y0 = ty * 8, x0 = tx * 16;
    const int tid = threadIdx.x;

    const float* __restrict__ x0p = x + (size_t)c * SSS;
    const float* __restrict__ x1p = x + (size_t)(CH + c) * SSS;

    if (tid < 125) { float w = w1[c*125 + tid]; swt[tid] = make_float2(w, w); }

    // halo: 20z x 12y x 20x
    for (int s = tid; s < 20*12*20; s += 128) {
        const int sz = s / 240, r = s % 240, sy = r / 20, sx = r % 20;
        const int gz = z0 - 2 + sz, gy = y0 - 2 + sy, gx = x0 - 2 + sx;
        float2 v = make_float2(0.f, 0.f);
        if ((unsigned)gz < 64u && (unsigned)gy < 64u && (unsigned)gx < 64u) {
            const int o = gz*SS + gy*64 + gx;
            v.x = x0p[o]; v.y = x1p[o];
        }
        sh[s] = v;
    }
    __syncthreads();

    const int lx = tid & 15, ly = tid >> 4;

    u64 acc[16];
    const float bias = b1[c];
    const u64 bpk = pk2(bias, bias);
#pragma unroll
    for (int z = 0; z < 16; z++) acc[z] = bpk;

#pragma unroll 1
    for (int ky = 0; ky < 5; ky++) {
        const int rowb = (ly + ky) * 20 + lx;
#pragma unroll 1
        for (int kx = 0; kx < 5; kx++) {
            u64 col[20];
#pragma unroll
            for (int j = 0; j < 20; j++)
                col[j] = *(const u64*)&sh[j*240 + rowb + kx];
#pragma unroll
            for (int kz = 0; kz < 5; kz++) {
                const u64 w = *(const u64*)&swt[kz*25 + ky*5 + kx];
#pragma unroll
                for (int z = 0; z < 16; z++)
                    ffma2(acc[z], col[z + kz], w);
            }
        }
    }

    // scatter into residue layout
    int ry, uy, rx, ux;
    r3(y0 + ly, ry, uy);
    r3(x0 + lx, rx, ux);
    float2* __restrict__ oc = (float2*)g_att1r + (size_t)c * RES_CH
                            + (ry*3 + rx)*RES_VOL + uy*RES_U + ux;
#pragma unroll
    for (int z = 0; z < 16; z++) {
        int rz, uz; r3(z0 + z, rz, uz);
        *(u64*)&oc[(size_t)rz*9*RES_VOL + uz*RES_UU] = acc[z];
    }
}

// ---------------- conv2: depthwise 7x7x7, dilation 3, pad 9 -----------------
// Residue decomposition (mod 3) -> dense 7-tap conv on subsampled grid.
// att1 source is residue layout -> halo loads are unit-stride coalesced.
// smem: x-stride 14 float2, z-plane stride padded to C2_ZS=200 float2.
// Phase addr mod 16 = lx + 8*hz -> conflict-free LDS.64. 47.5 KB static smem.
#define C2_ZS 200
__global__ __launch_bounds__(128) void k_conv2(const float* __restrict__ w2,
                                               const float* __restrict__ b2) {
    __shared__ float2 sh[28*C2_ZS];              // 44800 B
    __shared__ float2 swt[343];                  // 2744 B

    const int blk = blockIdx.x;                  // 27 residues * 9 yx tiles
    const int c = blockIdx.y;
    const int res = blk / 9, t = blk % 9;
    const int rz = res / 9, ry = (res / 3) % 3, rx = res % 3;
    const int tyi = t / 3, txi = t % 3;
    const int Lz = (rz == 0) ? 22 : 21;
    const int Ly = (ry == 0) ? 22 : 21;
    const int Lx = (rx == 0) ? 22 : 21;

    const int tid = threadIdx.x;
    const float2* __restrict__ icp = (const float2*)g_att1r + (size_t)c * RES_CH
                                   + (size_t)res * RES_VOL;
    for (int s = tid; s < 343; s += 128) { float w = w2[c*343 + s]; swt[s] = make_float2(w, w); }

    const int uy0 = tyi*8, ux0 = txi*8;
    // halo: 28 uz x 14 uy x 14 ux, coalesced (lanes -> ux consecutive)
    for (int cp = tid; cp < 196; cp += 128) {
        const int sy = cp / 14, sx = cp % 14;
        const int uyh = uy0 + sy - 3, uxh = ux0 + sx - 3;
        const bool vyx = ((unsigned)uyh < (unsigned)Ly) && ((unsigned)uxh < (unsigned)Lx);
        const float2* src = icp + uyh*RES_U + uxh;
        const int base = sy*14 + sx;
#pragma unroll 4
        for (int sz = 0; sz < 28; sz++) {
            const int uzh = sz - 3;
            float2 v = make_float2(0.f, 0.f);
            if (vyx && (unsigned)uzh < (unsigned)Lz)
                v = src[uzh*RES_UU];
            sh[sz*C2_ZS + base] = v;
        }
    }
    __syncthreads();

    const int lx = tid & 7;
    const int hz = (tid >> 3) & 1;               // z half: u 0..10 / 11..21
    const int ly = tid >> 4;                     // 0..7
    const int uy = uy0 + ly, ux = ux0 + lx;
    const int zb = 11*hz;

    u64 acc[11];
    const float bias = b2[c];
    const u64 bpk = pk2(bias, bias);
#pragma unroll
    for (int l = 0; l < 11; l++) acc[l] = bpk;

#pragma unroll 1
    for (int ky = 0; ky < 7; ky++) {
        const int rowb = (ly + ky)*14 + lx;
#pragma unroll
        for (int kx = 0; kx < 7; kx++) {
            u64 col[17];
#pragma unroll
            for (int j = 0; j < 17; j++)
                col[j] = *(const u64*)&sh[(zb + j)*C2_ZS + rowb + kx];
#pragma unroll
            for (int kz = 0; kz < 7; kz++) {
                const u64 w = *(const u64*)&swt[kz*49 + ky*7 + kx];
#pragma unroll
                for (int l = 0; l < 11; l++)
                    ffma2(acc[l], col[l+kz], w);
            }
        }
    }

    if (uy < Ly && ux < Lx) {
        float2* __restrict__ oc = (float2*)g_att2 + (size_t)c*SSS;
        const int gy = ry + 3*uy, gx = rx + 3*ux;
#pragma unroll
        for (int l = 0; l < 11; l++) {
            const int u = zb + l;
            if (u < Lz)
                *(u64*)&oc[(rz + 3*u)*SS + gy*64 + gx] = acc[l];
        }
    }
}

// ---------------- pool: channel mean + max over [att1; att2], both batches --
__global__ __launch_bounds__(256) void k_pool() {
    const int s = blockIdx.x * 256 + threadIdx.x;       // over SSS
    const int gz = s >> 12, gy = (s >> 6) & 63, gx = s & 63;
    int rz, uz, ry, uy, rx, ux;
    r3(gz, rz, uz); r3(gy, ry, uy); r3(gx, rx, ux);
    const size_t ridx = (size_t)(rz*9 + ry*3 + rx)*RES_VOL + uz*RES_UU + uy*RES_U + ux;

    const float2* p1 = (const float2*)g_att1r + ridx;
    const float2* p2 = (const float2*)g_att2 + s;
    float s0 = 0.f, s1 = 0.f, m0 = -INFINITY, m1 = -INFINITY;
#pragma unroll 8
    for (int c = 0; c < 64; c++) {
        float2 v = p1[(size_t)c*RES_CH];
        s0 += v.x; s1 += v.y; m0 = fmaxf(m0, v.x); m1 = fmaxf(m1, v.y);
    }
#pragma unroll 8
    for (int c = 0; c < 64; c++) {
        float2 v = p2[(size_t)c*SSS];
        s0 += v.x; s1 += v.y; m0 = fmaxf(m0, v.x); m1 = fmaxf(m1, v.y);
    }
    g_pooled2[s]       = make_float2(s0 * (1.f/128.f), s1 * (1.f/128.f));
    g_pooled2[SSS + s] = make_float2(m0, m1);
}

// ---------------- gate: 2->2 conv 7x7x7 pad 3, sigmoid (scalar, per batch) --
__global__ __launch_bounds__(128) void k_gate(const float* __restrict__ ws,
                                              const float* __restrict__ bs) {
    const int tile = blockIdx.x;                 // tz(8) ty(4) tx(8) = 256
    const int b = blockIdx.y;
    const int tz = tile >> 5, ty = (tile >> 3) & 3, tx = tile & 7;
    const int z0 = tz*8, y0 = ty*16, x0 = tx*8;

    __shared__ float sh[2*14*22*14];
    __shared__ float swt[1372];
    const int tid = threadIdx.x;

    for (int s = tid; s < 1372; s += 128) swt[s] = ws[s];
    for (int s = tid; s < 2*14*22*14; s += 128) {
        int icc = s / 4312, r = s % 4312;
        int sz = r / 308, r2 = r % 308, sy = r2 / 14, sx = r2 % 14;
        int gz = z0-3+sz, gy = y0-3+sy, gx = x0-3+sx;
        float v = 0.f;
        if ((unsigned)gz < 64u && (unsigned)gy < 64u && (unsigned)gx < 64u) {
            float2 p = g_pooled2[icc*SSS + gz*SS + gy*64 + gx];
            v = b ? p.y : p.x;
        }
        sh[s] = v;
    }
    __syncthreads();

    const int ly = tid >> 3, lx = tid & 7;
    float acc0[8], acc1[8];
    const float bias0 = bs[0], bias1 = bs[1];
#pragma unroll
    for (int z = 0; z < 8; z++) { acc0[z] = bias0; acc1[z] = bias1; }

#pragma unroll 1
    for (int icc = 0; icc < 2; icc++)
#pragma unroll 1
    for (int ky = 0; ky < 7; ky++)
#pragma unroll 1
    for (int kx = 0; kx < 7; kx++) {
        float col[14];
#pragma unroll
        for (int j = 0; j < 14; j++)
            col[j] = sh[icc*4312 + j*308 + (ly+ky)*14 + lx + kx];
#pragma unroll
        for (int kz = 0; kz < 7; kz++) {
            const float w0 = swt[icc*343 + kz*49 + ky*7 + kx];
            const float w1 = swt[686 + icc*343 + kz*49 + ky*7 + kx];
#pragma unroll
            for (int z = 0; z < 8; z++) {
                acc0[z] = fmaf(col[z+kz], w0, acc0[z]);
                acc1[z] = fmaf(col[z+kz], w1, acc1[z]);
            }
        }
    }

    float* g0 = g_gate + (size_t)b*2*SSS;
#pragma unroll
    for (int z = 0; z < 8; z++) {
        const int o = (z0+z)*SS + (y0+ly)*64 + (x0+lx);
        g0[o]       = 1.f/(1.f + __expf(-acc0[z]));
        g0[SSS + o] = 1.f/(1.f + __expf(-acc1[z]));
    }
}

// ---------------- combine: out = att1*g0 + att2*g1 + x ----------------------
// one float2 (both batches of one voxel) per thread; att1 read via residue map.
__global__ __launch_bounds__(256) void k_combine(const float* __restrict__ x,
                                                 float* __restrict__ out) {
    const int i = blockIdx.x * 256 + threadIdx.x;      // 16,777,216 threads
    const int c = i >> 18;                              // SSS f2 per channel
    const int s = i & (SSS - 1);
    const int gz = s >> 12, gy = (s >> 6) & 63, gx = s & 63;
    int rz, uz, ry, uy, rx, ux;
    r3(gz, rz, uz); r3(gy, ry, uy); r3(gx, rx, ux);
    const size_t ridx = (size_t)c*RES_CH
                      + (size_t)(rz*9 + ry*3 + rx)*RES_VOL + uz*RES_UU + uy*RES_U + ux;

    const float2 a1 = *((const float2*)g_att1r + ridx);
    const float2 a2 = *((const float2*)g_att2 + (size_t)c*SSS + s);
    const float g00 = g_gate[s];                 // b0, g0
    const float g01 = g_gate[SSS + s];           // b0, g1
    const float g10 = g_gate[2*SSS + s];         // b1, g0
    const float g11 = g_gate[3*SSS + s];         // b1, g1
    const float xv0 = x[(size_t)c*SSS + s];
    const float xv1 = x[(size_t)(CH + c)*SSS + s];

    out[(size_t)c*SSS + s]        = fmaf(a1.x, g00, fmaf(a2.x, g01, xv0));
    out[(size_t)(CH + c)*SSS + s] = fmaf(a1.y, g10, fmaf(a2.y, g11, xv1));
}

extern "C" void kernel_launch(void* const* d_in, const int* in_sizes, int n_in,
                              void* d_out, int out_size) {
    const float* x  = (const float*)d_in[0];
    const float* w1 = (const float*)d_in[1];
    const float* b1 = (const float*)d_in[2];
    const float* w2 = (const float*)d_in[3];
    const float* b2 = (const float*)d_in[4];
    const float* ws = (const float*)d_in[5];
    const float* bs = (const float*)d_in[6];
    float* out = (float*)d_out;

    k_conv1<<<dim3(128, 64), 128>>>(x, w1, b1);
    k_conv2<<<dim3(243, 64), 128>>>(w2, b2);
    k_pool<<<1024, 256>>>();
    k_gate<<<dim3(256, 2), 128>>>(ws, bs);
    k_combine<<<65536, 256>>>(x, out);
}

// round 16
// speedup vs baseline: 1.1794x; 1.0035x over previous
#include <cuda_runtime.h>
#include <math.h>

#define SS   4096      // 64*64
#define SSS  262144    // 64^3
#define CH   64

// residue layout constants
#define RES_U   22                 // padded u extent
#define RES_UU  484                // 22*22
#define RES_VOL 10648              // 22^3
#define RES_CH  287496             // 27 * 10648 (f2 per channel)

typedef unsigned long long u64;

// Scratch (device globals). att1 AND att2 stored residue-decomposed +
// batch-packed: element (c, r=(rz,ry,rx), uz, uy, ux) is float2 (b0, b1).
__device__ float4 g_att1r[CH*RES_CH/2 + 64];
__device__ float4 g_att2r[CH*RES_CH/2 + 64];
__device__ float2 g_pooled2[2*SSS];    // [ic={mean,max}][s] -> (b0,b1)
__device__ float  g_gate[2*2*SSS];     // [b][{g0,g1}][s]

__device__ __forceinline__ u64 pk2(float lo, float hi) {
    u64 r; asm("mov.b64 %0, {%1, %2};" : "=l"(r) : "f"(lo), "f"(hi)); return r;
}
__device__ __forceinline__ void ffma2(u64& d, u64 a, u64 b) {
    asm("fma.rn.f32x2 %0, %1, %2, %0;" : "+l"(d) : "l"(a), "l"(b));
}

// map natural (g) -> (r, u)
__device__ __forceinline__ void r3(int g, int& r, int& u) { u = g / 3; r = g - 3*u; }

// ---------------- conv1: depthwise 5x5x5, pad 2, both batches packed --------
// tile: z=16, y=8, x=16; 128 threads = lx(16) x ly(8); thread computes a
// z-column of 16 packed outputs. Warp phase = 16 contiguous lx ->
// conflict-free LDS.64. Output scattered into residue layout.
__global__ __launch_bounds__(128) void k_conv1(const float* __restrict__ x,
                                               const float* __restrict__ w1,
                                               const float* __restrict__ b1) {
    __shared__ float2 sh[20*12*20];              // 4800 f2 = 38400 B
    __shared__ float2 swt[125];

    const int bx = blockIdx.x, c = blockIdx.y;   // bx: tz(4) ty(8) tx(4)
    const int tz = bx >> 5, ty = (bx >> 2) & 7, tx = bx & 3;
    const int z0 = tz * 16, y0 = ty * 8, x0 = tx * 16;
    const int tid = threadIdx.x;

    const float* __restrict__ x0p = x + (size_t)c * SSS;
    const float* __restrict__ x1p = x + (size_t)(CH + c) * SSS;

    if (tid < 125) { float w = w1[c*125 + tid]; swt[tid] = make_float2(w, w); }

    // halo: 20z x 12y x 20x
    for (int s = tid; s < 20*12*20; s += 128) {
        const int sz = s / 240, r = s % 240, sy = r / 20, sx = r % 20;
        const int gz = z0 - 2 + sz, gy = y0 - 2 + sy, gx = x0 - 2 + sx;
        float2 v = make_float2(0.f, 0.f);
        if ((unsigned)gz < 64u && (unsigned)gy < 64u && (unsigned)gx < 64u) {
            const int o = gz*SS + gy*64 + gx;
            v.x = x0p[o]; v.y = x1p[o];
        }
        sh[s] = v;
    }
    __syncthreads();

    const int lx = tid & 15, ly = tid >> 4;

    u64 acc[16];
    const float bias = b1[c];
    const u64 bpk = pk2(bias, bias);
#pragma unroll
    for (int z = 0; z < 16; z++) acc[z] = bpk;

#pragma unroll 1
    for (int ky = 0; ky < 5; ky++) {
        const int rowb = (ly + ky) * 20 + lx;
#pragma unroll 1
        for (int kx = 0; kx < 5; kx++) {
            u64 col[20];
#pragma unroll
            for (int j = 0; j < 20; j++)
                col[j] = *(const u64*)&sh[j*240 + rowb + kx];
#pragma unroll
            for (int kz = 0; kz < 5; kz++) {
                const u64 w = *(const u64*)&swt[kz*25 + ky*5 + kx];
#pragma unroll
                for (int z = 0; z < 16; z++)
                    ffma2(acc[z], col[z + kz], w);
            }
        }
    }

    // scatter into residue layout
    int ry, uy, rx, ux;
    r3(y0 + ly, ry, uy);
    r3(x0 + lx, rx, ux);
    float2* __restrict__ oc = (float2*)g_att1r + (size_t)c * RES_CH
                            + (ry*3 + rx)*RES_VOL + uy*RES_U + ux;
#pragma unroll
    for (int z = 0; z < 16; z++) {
        int rz, uz; r3(z0 + z, rz, uz);
        *(u64*)&oc[(size_t)rz*9*RES_VOL + uz*RES_UU] = acc[z];
    }
}

// ---------------- conv2: depthwise 7x7x7, dilation 3, pad 9 -----------------
// Residue decomposition (mod 3) -> dense 7-tap conv on subsampled grid.
// att1 source AND att2 destination in residue layout -> fully coalesced
// gmem on both sides. smem: x-stride 14 f2, z-plane stride C2_ZS=200 f2.
// Phase addr mod 16 = lx + 8*hz -> conflict-free LDS.64. 47.5 KB static smem.
#define C2_ZS 200
__global__ __launch_bounds__(128) void k_conv2(const float* __restrict__ w2,
                                               const float* __restrict__ b2) {
    __shared__ float2 sh[28*C2_ZS];              // 44800 B
    __shared__ float2 swt[343];                  // 2744 B

    const int blk = blockIdx.x;                  // 27 residues * 9 yx tiles
    const int c = blockIdx.y;
    const int res = blk / 9, t = blk % 9;
    const int rz = res / 9, ry = (res / 3) % 3, rx = res % 3;
    const int tyi = t / 3, txi = t % 3;
    const int Lz = (rz == 0) ? 22 : 21;
    const int Ly = (ry == 0) ? 22 : 21;
    const int Lx = (rx == 0) ? 22 : 21;

    const int tid = threadIdx.x;
    const float2* __restrict__ icp = (const float2*)g_att1r + (size_t)c * RES_CH
                                   + (size_t)res * RES_VOL;
    for (int s = tid; s < 343; s += 128) { float w = w2[c*343 + s]; swt[s] = make_float2(w, w); }

    const int uy0 = tyi*8, ux0 = txi*8;
    // halo: 28 uz x 14 uy x 14 ux, coalesced (lanes -> ux consecutive)
    for (int cp = tid; cp < 196; cp += 128) {
        const int sy = cp / 14, sx = cp % 14;
        const int uyh = uy0 + sy - 3, uxh = ux0 + sx - 3;
        const bool vyx = ((unsigned)uyh < (unsigned)Ly) && ((unsigned)uxh < (unsigned)Lx);
        const float2* src = icp + uyh*RES_U + uxh;
        const int base = sy*14 + sx;
#pragma unroll 4
        for (int sz = 0; sz < 28; sz++) {
            const int uzh = sz - 3;
            float2 v = make_float2(0.f, 0.f);
            if (vyx && (unsigned)uzh < (unsigned)Lz)
                v = src[uzh*RES_UU];
            sh[sz*C2_ZS + base] = v;
        }
    }
    __syncthreads();

    const int lx = tid & 7;
    const int hz = (tid >> 3) & 1;               // z half: u 0..10 / 11..21
    const int ly = tid >> 4;                     // 0..7
    const int uy = uy0 + ly, ux = ux0 + lx;
    const int zb = 11*hz;

    u64 acc[11];
    const float bias = b2[c];
    const u64 bpk = pk2(bias, bias);
#pragma unroll
    for (int l = 0; l < 11; l++) acc[l] = bpk;

#pragma unroll 1
    for (int ky = 0; ky < 7; ky++) {
        const int rowb = (ly + ky)*14 + lx;
#pragma unroll
        for (int kx = 0; kx < 7; kx++) {
            u64 col[17];
#pragma unroll
            for (int j = 0; j < 17; j++)
                col[j] = *(const u64*)&sh[(zb + j)*C2_ZS + rowb + kx];
#pragma unroll
            for (int kz = 0; kz < 7; kz++) {
                const u64 w = *(const u64*)&swt[kz*49 + ky*7 + kx];
#pragma unroll
                for (int l = 0; l < 11; l++)
                    ffma2(acc[l], col[l+kz], w);
            }
        }
    }

    if (uy < Ly && ux < Lx) {
        float2* __restrict__ oc = (float2*)g_att2r + (size_t)c*RES_CH
                                + (size_t)res*RES_VOL + uy*RES_U + ux;
#pragma unroll
        for (int l = 0; l < 11; l++) {
            const int u = zb + l;
            if (u < Lz)
                *(u64*)&oc[u*RES_UU] = acc[l];
        }
    }
}

// ---------------- pool: channel mean + max over [att1; att2], both batches --
__global__ __launch_bounds__(256) void k_pool() {
    const int s = blockIdx.x * 256 + threadIdx.x;       // over SSS
    const int gz = s >> 12, gy = (s >> 6) & 63, gx = s & 63;
    int rz, uz, ry, uy, rx, ux;
    r3(gz, rz, uz); r3(gy, ry, uy); r3(gx, rx, ux);
    const size_t ridx = (size_t)(rz*9 + ry*3 + rx)*RES_VOL + uz*RES_UU + uy*RES_U + ux;

    const float2* p1 = (const float2*)g_att1r + ridx;
    const float2* p2 = (const float2*)g_att2r + ridx;
    float s0 = 0.f, s1 = 0.f, m0 = -INFINITY, m1 = -INFINITY;
#pragma unroll 8
    for (int c = 0; c < 64; c++) {
        float2 v = p1[(size_t)c*RES_CH];
        s0 += v.x; s1 += v.y; m0 = fmaxf(m0, v.x); m1 = fmaxf(m1, v.y);
    }
#pragma unroll 8
    for (int c = 0; c < 64; c++) {
        float2 v = p2[(size_t)c*RES_CH];
        s0 += v.x; s1 += v.y; m0 = fmaxf(m0, v.x); m1 = fmaxf(m1, v.y);
    }
    g_pooled2[s]       = make_float2(s0 * (1.f/128.f), s1 * (1.f/128.f));
    g_pooled2[SSS + s] = make_float2(m0, m1);
}

// ---------------- gate: 2->2 conv 7x7x7 pad 3, sigmoid (scalar, per batch) --
__global__ __launch_bounds__(128) void k_gate(const float* __restrict__ ws,
                                              const float* __restrict__ bs) {
    const int tile = blockIdx.x;                 // tz(8) ty(4) tx(8) = 256
    const int b = blockIdx.y;
    const int tz = tile >> 5, ty = (tile >> 3) & 3, tx = tile & 7;
    const int z0 = tz*8, y0 = ty*16, x0 = tx*8;

    __shared__ float sh[2*14*22*14];
    __shared__ float swt[1372];
    const int tid = threadIdx.x;

    for (int s = tid; s < 1372; s += 128) swt[s] = ws[s];
    for (int s = tid; s < 2*14*22*14; s += 128) {
        int icc = s / 4312, r = s % 4312;
        int sz = r / 308, r2 = r % 308, sy = r2 / 14, sx = r2 % 14;
        int gz = z0-3+sz, gy = y0-3+sy, gx = x0-3+sx;
        float v = 0.f;
        if ((unsigned)gz < 64u && (unsigned)gy < 64u && (unsigned)gx < 64u) {
            float2 p = g_pooled2[icc*SSS + gz*SS + gy*64 + gx];
            v = b ? p.y : p.x;
        }
        sh[s] = v;
    }
    __syncthreads();

    const int ly = tid >> 3, lx = tid & 7;
    float acc0[8], acc1[8];
    const float bias0 = bs[0], bias1 = bs[1];
#pragma unroll
    for (int z = 0; z < 8; z++) { acc0[z] = bias0; acc1[z] = bias1; }

#pragma unroll 1
    for (int icc = 0; icc < 2; icc++)
#pragma unroll 1
    for (int ky = 0; ky < 7; ky++)
#pragma unroll 1
    for (int kx = 0; kx < 7; kx++) {
        float col[14];
#pragma unroll
        for (int j = 0; j < 14; j++)
            col[j] = sh[icc*4312 + j*308 + (ly+ky)*14 + lx + kx];
#pragma unroll
        for (int kz = 0; kz < 7; kz++) {
            const float w0 = swt[icc*343 + kz*49 + ky*7 + kx];
            const float w1 = swt[686 + icc*343 + kz*49 + ky*7 + kx];
#pragma unroll
            for (int z = 0; z < 8; z++) {
                acc0[z] = fmaf(col[z+kz], w0, acc0[z]);
                acc1[z] = fmaf(col[z+kz], w1, acc1[z]);
            }
        }
    }

    float* g0 = g_gate + (size_t)b*2*SSS;
#pragma unroll
    for (int z = 0; z < 8; z++) {
        const int o = (z0+z)*SS + (y0+ly)*64 + (x0+lx);
        g0[o]       = 1.f/(1.f + __expf(-acc0[z]));
        g0[SSS + o] = 1.f/(1.f + __expf(-acc1[z]));
    }
}

// ---------------- combine: out = att1*g0 + att2*g1 + x ----------------------
// one float2 (both batches of one voxel) per thread; att1/att2 via residue map.
__global__ __launch_bounds__(256) void k_combine(const float* __restrict__ x,
                                                 float* __restrict__ out) {
    const int i = blockIdx.x * 256 + threadIdx.x;      // 16,777,216 threads
    const int c = i >> 18;                              // SSS f2 per channel
    const int s = i & (SSS - 1);
    const int gz = s >> 12, gy = (s >> 6) & 63, gx = s & 63;
    int rz, uz, ry, uy, rx, ux;
    r3(gz, rz, uz); r3(gy, ry, uy); r3(gx, rx, ux);
    const size_t ridx = (size_t)c*RES_CH
                      + (size_t)(rz*9 + ry*3 + rx)*RES_VOL + uz*RES_UU + uy*RES_U + ux;

    const float2 a1 = *((const float2*)g_att1r + ridx);
    const float2 a2 = *((const float2*)g_att2r + ridx);
    const float g00 = g_gate[s];                 // b0, g0
    const float g01 = g_gate[SSS + s];           // b0, g1
    const float g10 = g_gate[2*SSS + s];         // b1, g0
    const float g11 = g_gate[3*SSS + s];         // b1, g1
    const float xv0 = x[(size_t)c*SSS + s];
    const float xv1 = x[(size_t)(CH + c)*SSS + s];

    out[(size_t)c*SSS + s]        = fmaf(a1.x, g00, fmaf(a2.x, g01, xv0));
    out[(size_t)(CH + c)*SSS + s] = fmaf(a1.y, g10, fmaf(a2.y, g11, xv1));
}

extern "C" void kernel_launch(void* const* d_in, const int* in_sizes, int n_in,
                              void* d_out, int out_size) {
    const float* x  = (const float*)d_in[0];
    const float* w1 = (const float*)d_in[1];
    const float* b1 = (const float*)d_in[2];
    const float* w2 = (const float*)d_in[3];
    const float* b2 = (const float*)d_in[4];
    const float* ws = (const float*)d_in[5];
    const float* bs = (const float*)d_in[6];
    float* out = (float*)d_out;

    k_conv1<<<dim3(128, 64), 128>>>(x, w1, b1);
    k_conv2<<<dim3(243, 64), 128>>>(w2, b2);
    k_pool<<<1024, 256>>>();
    k_gate<<<dim3(256, 2), 128>>>(ws, bs);
    k_combine<<<65536, 256>>>(x, out);
}